// round 14
// baseline (speedup 1.0000x reference)
#include <cuda_runtime.h>
#include <cuda_fp16.h>
#include <cstdint>
#include <math.h>

#define B_DIM 4
#define S_DIM 2048
#define T_DIM 256
#define H_DIM 2048
#define NHEAD 16
#define HD_DIM 128

#define BK 16
#define STAGE_PITCH 68       // fp32 epilogue staging pitch

// fp16 2-term GEMM: 128x128 tile, BK=16, 4-stage ring (12KB/stage), 2 CTAs/SM
#define FT 4096
#define FSTG 12288
#define SMEM_BYTES 49152

// Fused attention (64 q-rows per CTA, occ 2)
#define AS_KH 2048           // K-hi tile offset in scores stage (Q 64x16 at 0)
#define AS_KL 10240
#define AS_STG 18432         // stage = Q 2K + Kh 8K + Kl 8K
#define AS_PCH 2048          // P chunk tile bytes (64x16 fp16)
#define AS_VOFF 57344        // V ring after stages (3x18432 = 55296, aligned up)
#define AS_SMEM (AS_VOFF + 3*8192)   // 81920

// ---------------------------------------------------------------------------
// Persistent scratch
// ---------------------------------------------------------------------------
__device__ __half g_hs16[8192*2048];
__device__ __half g_at16h[1024*2048], g_at16l[1024*2048];
__device__ __half g_Wq16h[2048*2048], g_Wq16l[2048*2048];
__device__ __half g_Wk16h[2048*2048], g_Wk16l[2048*2048];
__device__ __half g_Wv16[2048*2048];
__device__ __half g_Wo16h[2048*2048], g_Wo16l[2048*2048];
__device__ __half g_Q16[8192*2048];
__device__ __half g_K16h[1024*2048], g_K16l[1024*2048];
__device__ __half g_Vt16h[64*128*256], g_Vt16l[64*128*256];
__device__ __half g_C16[8192*2048];
__device__ float  g_D[8192*2048];

// ---------------------------------------------------------------------------
// Helpers
// ---------------------------------------------------------------------------
__device__ __forceinline__ uint32_t smem_to_u32(const void* p) {
    uint32_t a;
    asm("{ .reg .u64 t; cvta.to.shared.u64 t, %1; cvt.u32.u64 %0, t; }" : "=r"(a) : "l"(p));
    return a;
}
__device__ __forceinline__ void cp16(uint32_t dst, const void* src) {
    asm volatile("cp.async.cg.shared.global [%0], [%1], 16;" :: "r"(dst), "l"(src));
}
#define CP_COMMIT() asm volatile("cp.async.commit_group;")
#define CP_WAIT1()  asm volatile("cp.async.wait_group 1;")
#define CP_WAIT2()  asm volatile("cp.async.wait_group 2;")

__device__ __forceinline__ void ldmx4(uint32_t* r, uint32_t addr) {
    asm volatile("ldmatrix.sync.aligned.m8n8.x4.shared.b16 {%0,%1,%2,%3}, [%4];"
                 : "=r"(r[0]), "=r"(r[1]), "=r"(r[2]), "=r"(r[3]) : "r"(addr));
}
__device__ __forceinline__ void mma16816h(float* c, const uint32_t* a, const uint32_t* b) {
    asm volatile("mma.sync.aligned.m16n8k16.row.col.f32.f16.f16.f32 "
                 "{%0,%1,%2,%3}, {%4,%5,%6,%7}, {%8,%9}, {%0,%1,%2,%3};"
                 : "+f"(c[0]), "+f"(c[1]), "+f"(c[2]), "+f"(c[3])
                 : "r"(a[0]), "r"(a[1]), "r"(a[2]), "r"(a[3]), "r"(b[0]), "r"(b[1]));
}
__device__ __forceinline__ void split_pair_f16(float x0, float x1, uint32_t& hi, uint32_t& lo) {
    __half2 h = __floats2half2_rn(x0, x1);
    float r0 = x0 - __half2float(__low2half(h));
    float r1 = x1 - __half2float(__high2half(h));
    __half2 l = __floats2half2_rn(r0, r1);
    hi = *(uint32_t*)&h;
    lo = *(uint32_t*)&l;
}
__device__ __forceinline__ uint32_t pack_h2(float x0, float x1) {
    __half2 h = __floats2half2_rn(x0, x1);
    return *(uint32_t*)&h;
}
__device__ __forceinline__ uint32_t swz(int row, int seg) {
    return (row >> 7) * 4096 + (row & 127) * 32 + ((seg << 4) ^ ((row & 4) << 2));
}

// ---------------------------------------------------------------------------
// Pre-pass kernels
// ---------------------------------------------------------------------------
__global__ void split16_kernel(const float* __restrict__ in,
                               __half* __restrict__ hi, __half* __restrict__ lo)
{
    int idx = blockIdx.x * blockDim.x + threadIdx.x;
    float4 v = ((const float4*)in)[idx];
    uint32_t h0, l0, h1, l1;
    split_pair_f16(v.x, v.y, h0, l0);
    split_pair_f16(v.z, v.w, h1, l1);
    ((uint2*)hi)[idx] = make_uint2(h0, h1);
    ((uint2*)lo)[idx] = make_uint2(l0, l1);
}
__global__ void cast16_kernel(const float* __restrict__ in, __half* __restrict__ out)
{
    int idx = blockIdx.x * blockDim.x + threadIdx.x;
    float4 v = ((const float4*)in)[idx];
    ((uint2*)out)[idx] = make_uint2(pack_h2(v.x, v.y), pack_h2(v.z, v.w));
}

// ---------------------------------------------------------------------------
// fp16 2-term GEMM: C = Ah*(Bh+Bl). 4-stage ring, 2 CTAs/SM.
//   MODE 0: +bias[col] -> fp16 single (Q-proj)
//   MODE 1: +bias[col] -> fp16 hi/lo pair (K-proj)
//   MODE 2: +bias[row] -> fp16 hi/lo Vt scatter (V-proj, A=Wv B=at)
//   MODE 4: +bias[col] -> fp32 (O-proj)
// ---------------------------------------------------------------------------
template<int MODE>
__global__ void __launch_bounds__(256, 2)
mma_gemm_f16(const __half* __restrict__ Ah, const __half* __restrict__ Bh,
             const __half* __restrict__ Bl, const float* __restrict__ bias,
             float* __restrict__ Cf, __half* __restrict__ C1,
             __half* __restrict__ Ch, __half* __restrict__ Cl,
             int K, int lda, int ldb, int ldc)
{
    __shared__ __align__(16) char smem[SMEM_BYTES];
    const int tid = threadIdx.x;
    const int wid = tid >> 5;
    const int lane = tid & 31;
    const int g = lane >> 2, ti = lane & 3;
    const int mwb = (wid >> 2) * 64;
    const int nwb = (wid & 3) * 32;
    const uint32_t sbase = smem_to_u32(smem);

    const int m0 = blockIdx.y * 128;
    const int n0 = blockIdx.x * 128;

    const int crow = tid >> 1;
    const int cseg = tid & 1;
    const size_t asrc = (size_t)(m0 + crow) * lda + cseg * 8;
    const size_t bsrc = (size_t)(n0 + crow) * ldb + cseg * 8;
    const uint32_t cdst = swz(crow, cseg);

    const int nchunk = K / BK;

    auto issue = [&](int c) {
        const uint32_t st = sbase + (c & 3) * FSTG;
        const int kt = c * BK;
        cp16(st + cdst,          Ah + asrc + kt);
        cp16(st + cdst + FT,     Bh + bsrc + kt);
        cp16(st + cdst + 2*FT,   Bl + bsrc + kt);
    };

    float acc[4][4][4];
#pragma unroll
    for (int i = 0; i < 4; i++)
#pragma unroll
        for (int j = 0; j < 4; j++)
#pragma unroll
            for (int q = 0; q < 4; q++) acc[i][j][q] = 0.f;

    issue(0); CP_COMMIT();
    issue(1); CP_COMMIT();
    issue(2); CP_COMMIT();

    const int arow = lane & 15;
    const int aseg = lane >> 4;
    const int brow = (lane & 7) + ((lane >> 4) << 3);
    const int bseg = (lane >> 3) & 1;

    for (int c = 0; c < nchunk; c++) {
        CP_WAIT2();
        __syncthreads();
        if (c + 3 < nchunk) issue(c + 3);
        CP_COMMIT();

        const uint32_t sbuf = sbase + (c & 3) * FSTG;
        uint32_t ah[4][4];
#pragma unroll
        for (int mf = 0; mf < 4; mf++)
            ldmx4(ah[mf], sbuf + swz(mwb + mf * 16 + arow, aseg));
#pragma unroll
        for (int np = 0; np < 2; np++) {
            uint32_t rh[4], rl[4];
            uint32_t bd = sbuf + FT + swz(nwb + np * 16 + brow, bseg);
            ldmx4(rh, bd);
            ldmx4(rl, bd + FT);
#pragma unroll
            for (int mf = 0; mf < 4; mf++) {
                mma16816h(acc[mf][2*np],   ah[mf], rh);
                mma16816h(acc[mf][2*np+1], ah[mf], rh + 2);
                mma16816h(acc[mf][2*np],   ah[mf], rl);
                mma16816h(acc[mf][2*np+1], ah[mf], rl + 2);
            }
        }
    }
    __syncthreads();

    float* stage = (float*)smem;
#pragma unroll
    for (int p = 0; p < 2; p++) {
        if (p) __syncthreads();
#pragma unroll
        for (int mf = 0; mf < 4; mf++)
#pragma unroll
            for (int e = 0; e < 2; e++) {
                const int nf = 2 * p + e;
                const int row = mwb + mf * 16 + g;
                const int cm = (wid & 3) * 16 + e * 8 + ti * 2;
                *(float2*)&stage[row * STAGE_PITCH + cm] =
                    make_float2(acc[mf][nf][0], acc[mf][nf][1]);
                *(float2*)&stage[(row + 8) * STAGE_PITCH + cm] =
                    make_float2(acc[mf][nf][2], acc[mf][nf][3]);
            }
        __syncthreads();
#pragma unroll
        for (int it = 0; it < 8; it++) {
            const int lin = it * 1024 + tid * 4;
            const int row = lin >> 6;
            const int cm = lin & 63;
            const int col = ((cm >> 4) << 5) + (p << 4) + (cm & 15);
            float4 v = *(float4*)&stage[row * STAGE_PITCH + cm];
            if (MODE == 0) {
                float4 b4 = *(const float4*)(bias + n0 + col);
                size_t off = (size_t)(m0 + row) * ldc + n0 + col;
                *(uint2*)(C1 + off) = make_uint2(pack_h2(v.x + b4.x, v.y + b4.y),
                                                 pack_h2(v.z + b4.z, v.w + b4.w));
            } else if (MODE == 1) {
                float4 b4 = *(const float4*)(bias + n0 + col);
                size_t off = (size_t)(m0 + row) * ldc + n0 + col;
                uint32_t h0, l0, h1, l1;
                split_pair_f16(v.x + b4.x, v.y + b4.y, h0, l0);
                split_pair_f16(v.z + b4.z, v.w + b4.w, h1, l1);
                *(uint2*)(Ch + off) = make_uint2(h0, h1);
                *(uint2*)(Cl + off) = make_uint2(l0, l1);
            } else if (MODE == 2) {
                const int gr = m0 + row;             // feature = h*128+d
                const int h = gr >> 7, d = gr & 127;
                const int n = n0 + col;              // b*256+t
                const int b = n >> 8, t = n & 255;
                const float br = bias[gr];
                size_t off = ((size_t)(b * NHEAD + h) * HD_DIM + d) * T_DIM + t;
                uint32_t h0, l0, h1, l1;
                split_pair_f16(v.x + br, v.y + br, h0, l0);
                split_pair_f16(v.z + br, v.w + br, h1, l1);
                *(uint2*)(Ch + off) = make_uint2(h0, h1);
                *(uint2*)(Cl + off) = make_uint2(l0, l1);
            } else {  // MODE 4
                float4 b4 = *(const float4*)(bias + n0 + col);
                float4 o = make_float4(v.x + b4.x, v.y + b4.y, v.z + b4.z, v.w + b4.w);
                *(float4*)(Cf + (size_t)(m0 + row) * ldc + n0 + col) = o;
            }
        }
    }
}

// ---------------------------------------------------------------------------
// Fused attention: 64 q-rows per CTA, 2 CTAs/SM, all fp16 2-term.
//  scores (warp tile 32x64) -> softmax -> P fp16 SMEM tiles -> PV (warp 32x32)
// ---------------------------------------------------------------------------
__global__ void __launch_bounds__(256, 2)
fused_attn_kernel(const __half* __restrict__ Q16,
                  const __half* __restrict__ K16h, const __half* __restrict__ K16l,
                  const __half* __restrict__ V16h, const __half* __restrict__ V16l,
                  const int* __restrict__ mask, __half* __restrict__ C16)
{
    extern __shared__ __align__(16) char dsm[];
    __shared__ float red[64][4];
    __shared__ int smask[T_DIM];

    const int tid = threadIdx.x;
    const int wid = tid >> 5;
    const int lane = tid & 31;
    const int g = lane >> 2, ti = lane & 3;
    const int mwb = (wid >> 2) * 32;      // m offset (0 or 32)
    const int nwb = (wid & 3) * 64;       // scores n offset
    const uint32_t sbase = smem_to_u32(dsm);

    const int m0 = blockIdx.y * 64;
    const int z = blockIdx.z;
    const int bb = z >> 4, hh = z & 15;
    const __half* pQ  = Q16  + (size_t)bb * S_DIM * H_DIM + hh * HD_DIM;
    const __half* pKh = K16h + (size_t)bb * T_DIM * H_DIM + hh * HD_DIM;
    const __half* pKl = K16l + (size_t)bb * T_DIM * H_DIM + hh * HD_DIM;

    smask[tid] = mask[bb * T_DIM + tid];

    const int crow = tid >> 1, cseg = tid & 1;
    const size_t qsrc  = (size_t)(m0 + crow) * H_DIM + cseg * 8;   // crow<64 for tid<128
    const size_t ksrc0 = (size_t)crow * H_DIM + cseg * 8;
    const size_t ksrc1 = (size_t)(crow + 128) * H_DIM + cseg * 8;
    const uint32_t adst = swz(crow, cseg);
    const uint32_t bdst0 = swz(crow, cseg);
    const uint32_t bdst1 = swz(crow + 128, cseg);

    auto issue = [&](int c) {
        const uint32_t st = sbase + (c % 3) * AS_STG;
        const int kt = c * BK;
        if (tid < 128) cp16(st + adst, pQ + qsrc + kt);   // Q 64x16
        cp16(st + AS_KH + bdst0,   pKh + ksrc0 + kt);
        cp16(st + AS_KH + bdst1,   pKh + ksrc1 + kt);
        cp16(st + AS_KL + bdst0,   pKl + ksrc0 + kt);
        cp16(st + AS_KL + bdst1,   pKl + ksrc1 + kt);
    };

    float acc[2][8][4];
#pragma unroll
    for (int i = 0; i < 2; i++)
#pragma unroll
        for (int j = 0; j < 8; j++)
#pragma unroll
            for (int q = 0; q < 4; q++) acc[i][j][q] = 0.f;

    issue(0); CP_COMMIT();
    issue(1); CP_COMMIT();

    const int arow = lane & 15;
    const int aseg = lane >> 4;
    const int brow = (lane & 7) + ((lane >> 4) << 3);
    const int bseg = (lane >> 3) & 1;

    for (int c = 0; c < 8; c++) {          // K = HD = 128
        CP_WAIT1();
        __syncthreads();
        if (c + 2 < 8) issue(c + 2);
        CP_COMMIT();

        const uint32_t sbuf = sbase + (c % 3) * AS_STG;
        uint32_t ah[2][4];
#pragma unroll
        for (int mf = 0; mf < 2; mf++)
            ldmx4(ah[mf], sbuf + swz(mwb + mf * 16 + arow, aseg));
#pragma unroll
        for (int np = 0; np < 4; np++) {
            uint32_t rh[4], rl[4];
            uint32_t bd = sbuf + AS_KH + swz(nwb + np * 16 + brow, bseg);
            ldmx4(rh, bd);
            ldmx4(rl, bd + (AS_KL - AS_KH));
#pragma unroll
            for (int mf = 0; mf < 2; mf++) {
                mma16816h(acc[mf][2*np],   ah[mf], rh);
                mma16816h(acc[mf][2*np+1], ah[mf], rh + 2);
                mma16816h(acc[mf][2*np],   ah[mf], rl);
                mma16816h(acc[mf][2*np+1], ah[mf], rl + 2);
            }
        }
    }

    // Prefetch first V tiles (region does not overlap scores stages)
    const __half* pVh = V16h + (size_t)z * HD_DIM * T_DIM;
    const __half* pVl = V16l + (size_t)z * HD_DIM * T_DIM;
    const size_t vsrc = (size_t)crow * T_DIM + cseg * 8;
    const uint32_t vdst = swz(crow, cseg);
    auto issueV = [&](int c) {
        const uint32_t st = sbase + AS_VOFF + (c % 3) * 8192;
        cp16(st + vdst,        pVh + vsrc + c * 16);
        cp16(st + vdst + 4096, pVl + vsrc + c * 16);
    };
    issueV(0); CP_COMMIT();
    issueV(1); CP_COMMIT();
    __syncthreads();   // all warps done with scores stages before P overwrite

    // ---- mask/scale/clip + per-row softmax (rows span 4 n-warps) ----
    const float invs = 0.08838834764831845f;   // 1/sqrt(128)
    float rmax[2][2], rsum[2][2];
#pragma unroll
    for (int mf = 0; mf < 2; mf++) {
        float mx0 = -1e30f, mx1 = -1e30f;
#pragma unroll
        for (int nf = 0; nf < 8; nf++) {
            const int col = nwb + nf * 8 + ti * 2;
            const bool k0 = smask[col] != 0;
            const bool k1 = smask[col + 1] != 0;
            float* a = acc[mf][nf];
            a[0] = k0 ? fminf(fmaxf(a[0] * invs, -50.f), 50.f) : -50.f;
            a[1] = k1 ? fminf(fmaxf(a[1] * invs, -50.f), 50.f) : -50.f;
            a[2] = k0 ? fminf(fmaxf(a[2] * invs, -50.f), 50.f) : -50.f;
            a[3] = k1 ? fminf(fmaxf(a[3] * invs, -50.f), 50.f) : -50.f;
            mx0 = fmaxf(mx0, fmaxf(a[0], a[1]));
            mx1 = fmaxf(mx1, fmaxf(a[2], a[3]));
        }
        mx0 = fmaxf(mx0, __shfl_xor_sync(0xffffffffu, mx0, 1));
        mx0 = fmaxf(mx0, __shfl_xor_sync(0xffffffffu, mx0, 2));
        mx1 = fmaxf(mx1, __shfl_xor_sync(0xffffffffu, mx1, 1));
        mx1 = fmaxf(mx1, __shfl_xor_sync(0xffffffffu, mx1, 2));
        if (ti == 0) {
            red[mwb + mf * 16 + g][wid & 3]     = mx0;
            red[mwb + mf * 16 + g + 8][wid & 3] = mx1;
        }
    }
    __syncthreads();
#pragma unroll
    for (int mf = 0; mf < 2; mf++) {
        float4 r0 = *(float4*)red[mwb + mf * 16 + g];
        rmax[mf][0] = fmaxf(fmaxf(r0.x, r0.y), fmaxf(r0.z, r0.w));
        float4 r1 = *(float4*)red[mwb + mf * 16 + g + 8];
        rmax[mf][1] = fmaxf(fmaxf(r1.x, r1.y), fmaxf(r1.z, r1.w));
    }
    __syncthreads();
#pragma unroll
    for (int mf = 0; mf < 2; mf++) {
        float s0 = 0.f, s1 = 0.f;
#pragma unroll
        for (int nf = 0; nf < 8; nf++) {
            float* a = acc[mf][nf];
            a[0] = __expf(a[0] - rmax[mf][0]); s0 += a[0];
            a[1] = __expf(a[1] - rmax[mf][0]); s0 += a[1];
            a[2] = __expf(a[2] - rmax[mf][1]); s1 += a[2];
            a[3] = __expf(a[3] - rmax[mf][1]); s1 += a[3];
        }
        s0 += __shfl_xor_sync(0xffffffffu, s0, 1);
        s0 += __shfl_xor_sync(0xffffffffu, s0, 2);
        s1 += __shfl_xor_sync(0xffffffffu, s1, 1);
        s1 += __shfl_xor_sync(0xffffffffu, s1, 2);
        if (ti == 0) {
            red[mwb + mf * 16 + g][wid & 3]     = s0;
            red[mwb + mf * 16 + g + 8][wid & 3] = s1;
        }
    }
    __syncthreads();
#pragma unroll
    for (int mf = 0; mf < 2; mf++) {
        float4 r0 = *(float4*)red[mwb + mf * 16 + g];
        rsum[mf][0] = 1.f / (r0.x + r0.y + r0.z + r0.w);
        float4 r1 = *(float4*)red[mwb + mf * 16 + g + 8];
        rsum[mf][1] = 1.f / (r1.x + r1.y + r1.z + r1.w);
    }

    // ---- stage P (single fp16) into SMEM A-operand tiles: chunk ch at ch*2048 ----
#pragma unroll
    for (int mf = 0; mf < 2; mf++) {
        const int r0 = mwb + mf * 16 + g;
#pragma unroll
        for (int nf = 0; nf < 8; nf++) {
            const int col = nwb + nf * 8 + ti * 2;
            const int ch = col >> 4;
            const int colc = col & 15;
            const uint32_t cb = ch * AS_PCH + (((colc >> 3) << 4) ^ ((r0 & 4) << 2))
                              + (colc & 7) * 2 + r0 * 32;
            float* a = acc[mf][nf];
            *(uint32_t*)(dsm + cb)       = pack_h2(a[0] * rsum[mf][0], a[1] * rsum[mf][0]);
            *(uint32_t*)(dsm + cb + 256) = pack_h2(a[2] * rsum[mf][1], a[3] * rsum[mf][1]);
        }
    }
    __syncthreads();

    // ---- PV mainloop: ctx[64 s][128 d], K = T = 256, 16 chunks ----
    float ctx[2][4][4];
#pragma unroll
    for (int i = 0; i < 2; i++)
#pragma unroll
        for (int j = 0; j < 4; j++)
#pragma unroll
            for (int q = 0; q < 4; q++) ctx[i][j][q] = 0.f;

    const int nwb2 = (wid & 3) * 32;
    for (int c = 0; c < 16; c++) {
        CP_WAIT1();
        __syncthreads();
        if (c + 2 < 16) issueV(c + 2);
        CP_COMMIT();

        const uint32_t pbuf = sbase + c * AS_PCH;
        const uint32_t vbuf = sbase + AS_VOFF + (c % 3) * 8192;
        uint32_t ah[2][4];
#pragma unroll
        for (int mf = 0; mf < 2; mf++)
            ldmx4(ah[mf], pbuf + swz(mwb + mf * 16 + arow, aseg));
#pragma unroll
        for (int np = 0; np < 2; np++) {
            uint32_t rh[4], rl[4];
            uint32_t bd = vbuf + swz(nwb2 + np * 16 + brow, bseg);
            ldmx4(rh, bd);
            ldmx4(rl, bd + 4096);
#pragma unroll
            for (int mf = 0; mf < 2; mf++) {
                mma16816h(ctx[mf][2*np],   ah[mf], rh);
                mma16816h(ctx[mf][2*np+1], ah[mf], rh + 2);
                mma16816h(ctx[mf][2*np],   ah[mf], rl);
                mma16816h(ctx[mf][2*np+1], ah[mf], rl + 2);
            }
        }
    }
    __syncthreads();

    // ---- ctx scatter -> single fp16 [b*S+s, h*128+d] (64 rows) ----
    float* stage = (float*)dsm;
#pragma unroll
    for (int p = 0; p < 2; p++) {
        if (p) __syncthreads();
#pragma unroll
        for (int mf = 0; mf < 2; mf++)
#pragma unroll
            for (int e = 0; e < 2; e++) {
                const int nf = 2 * p + e;
                const int row = mwb + mf * 16 + g;
                const int cm = (wid & 3) * 16 + e * 8 + ti * 2;
                *(float2*)&stage[row * STAGE_PITCH + cm] =
                    make_float2(ctx[mf][nf][0], ctx[mf][nf][1]);
                *(float2*)&stage[(row + 8) * STAGE_PITCH + cm] =
                    make_float2(ctx[mf][nf][2], ctx[mf][nf][3]);
            }
        __syncthreads();
#pragma unroll
        for (int it = 0; it < 4; it++) {
            const int lin = it * 1024 + tid * 4;
            const int row = lin >> 6;
            const int cm = lin & 63;
            const int col = ((cm >> 4) << 5) + (p << 4) + (cm & 15);
            float4 v = *(float4*)&stage[row * STAGE_PITCH + cm];
            size_t off = (size_t)(bb * S_DIM + m0 + row) * H_DIM + hh * HD_DIM + col;
            *(uint2*)(C16 + off) = make_uint2(pack_h2(v.x, v.y), pack_h2(v.z, v.w));
        }
    }
}

// ---------------------------------------------------------------------------
// LayerNorm
// ---------------------------------------------------------------------------
__device__ __forceinline__ float block_sum(float v)
{
    __shared__ float red[8];
#pragma unroll
    for (int o = 16; o; o >>= 1) v += __shfl_xor_sync(0xffffffffu, v, o);
    int w = threadIdx.x >> 5;
    if ((threadIdx.x & 31) == 0) red[w] = v;
    __syncthreads();
    float t = (threadIdx.x < 8) ? red[threadIdx.x] : 0.f;
    if (threadIdx.x < 32) {
#pragma unroll
        for (int o = 4; o; o >>= 1) t += __shfl_xor_sync(0xffffffffu, t, o);
        if (threadIdx.x == 0) red[0] = t;
    }
    __syncthreads();
    float r = red[0];
    __syncthreads();
    return r;
}

__global__ void ln_kernel(const float* __restrict__ D, const float* __restrict__ gamma,
                          const float* __restrict__ beta, const float* __restrict__ rsp,
                          float* __restrict__ out)
{
    int row = blockIdx.x;
    int tid = threadIdx.x;
    float rs = fminf(fmaxf(rsp[0], 0.f), 0.3f);

    const float* d = D + (size_t)row * H_DIM;
    float4 u0 = *(const float4*)(d + tid * 4);
    float4 u1 = *(const float4*)(d + 1024 + tid * 4);
    float x[8] = {rs*u0.x, rs*u0.y, rs*u0.z, rs*u0.w,
                  rs*u1.x, rs*u1.y, rs*u1.z, rs*u1.w};

    float ps = 0.f;
#pragma unroll
    for (int i = 0; i < 8; i++) ps += x[i];
    float mean = block_sum(ps) * (1.f / 2048.f);

    float pv = 0.f;
#pragma unroll
    for (int i = 0; i < 8; i++) { float dd = x[i] - mean; pv += dd * dd; }
    float var = block_sum(pv) * (1.f / 2048.f);
    float inv = rsqrtf(var + 1e-5f);

    float4 gz0 = *(const float4*)(gamma + tid * 4);
    float4 gz1 = *(const float4*)(gamma + 1024 + tid * 4);
    float4 bz0 = *(const float4*)(beta + tid * 4);
    float4 bz1 = *(const float4*)(beta + 1024 + tid * 4);

    float* o = out + (size_t)row * H_DIM;
    *(float4*)(o + tid * 4) = make_float4(
        (x[0]-mean)*inv*gz0.x + bz0.x, (x[1]-mean)*inv*gz0.y + bz0.y,
        (x[2]-mean)*inv*gz0.z + bz0.z, (x[3]-mean)*inv*gz0.w + bz0.w);
    *(float4*)(o + 1024 + tid * 4) = make_float4(
        (x[4]-mean)*inv*gz1.x + bz1.x, (x[5]-mean)*inv*gz1.y + bz1.y,
        (x[6]-mean)*inv*gz1.z + bz1.z, (x[7]-mean)*inv*gz1.w + bz1.w);
}

// ---------------------------------------------------------------------------
// Launch
// ---------------------------------------------------------------------------
extern "C" void kernel_launch(void* const* d_in, const int* in_sizes, int n_in,
                              void* d_out, int out_size)
{
    const float* hs    = (const float*)d_in[0];
    const float* at    = (const float*)d_in[1];
    const int*   mask  = (const int*)  d_in[2];
    const float* Wq    = (const float*)d_in[3];
    const float* bq    = (const float*)d_in[4];
    const float* Wk    = (const float*)d_in[5];
    const float* bk    = (const float*)d_in[6];
    const float* Wv    = (const float*)d_in[7];
    const float* bv    = (const float*)d_in[8];
    const float* Wo    = (const float*)d_in[9];
    const float* bo    = (const float*)d_in[10];
    const float* gamma = (const float*)d_in[11];
    const float* beta  = (const float*)d_in[12];
    const float* rsp   = (const float*)d_in[13];
    float* out = (float*)d_out;

    __half *hs16, *at16h, *at16l, *Wq16h, *Wq16l, *Wk16h, *Wk16l, *Wv16, *Wo16h, *Wo16l;
    __half *Q16, *K16h, *K16l, *Vt16h, *Vt16l, *C16;
    float *Db;
    cudaGetSymbolAddress((void**)&hs16,  g_hs16);
    cudaGetSymbolAddress((void**)&at16h, g_at16h); cudaGetSymbolAddress((void**)&at16l, g_at16l);
    cudaGetSymbolAddress((void**)&Wq16h, g_Wq16h); cudaGetSymbolAddress((void**)&Wq16l, g_Wq16l);
    cudaGetSymbolAddress((void**)&Wk16h, g_Wk16h); cudaGetSymbolAddress((void**)&Wk16l, g_Wk16l);
    cudaGetSymbolAddress((void**)&Wv16,  g_Wv16);
    cudaGetSymbolAddress((void**)&Wo16h, g_Wo16h); cudaGetSymbolAddress((void**)&Wo16l, g_Wo16l);
    cudaGetSymbolAddress((void**)&Q16,   g_Q16);
    cudaGetSymbolAddress((void**)&K16h,  g_K16h);  cudaGetSymbolAddress((void**)&K16l,  g_K16l);
    cudaGetSymbolAddress((void**)&Vt16h, g_Vt16h); cudaGetSymbolAddress((void**)&Vt16l, g_Vt16l);
    cudaGetSymbolAddress((void**)&C16,   g_C16);
    cudaGetSymbolAddress((void**)&Db,    g_D);

    cudaFuncSetAttribute(fused_attn_kernel,
                         cudaFuncAttributeMaxDynamicSharedMemorySize, AS_SMEM);

    // Pre-pass
    cast16_kernel<<<16384, 256>>>(hs, hs16);
    cast16_kernel<<<4096, 256>>>(Wv, Wv16);
    split16_kernel<<<2048, 256>>>(at, at16h, at16l);
    split16_kernel<<<4096, 256>>>(Wq, Wq16h, Wq16l);
    split16_kernel<<<4096, 256>>>(Wk, Wk16h, Wk16l);
    split16_kernel<<<4096, 256>>>(Wo, Wo16h, Wo16l);

    // Q projection -> fp16 single
    mma_gemm_f16<0><<<dim3(16, 64), 256>>>(hs16, Wq16h, Wq16l, bq,
                                           nullptr, Q16, nullptr, nullptr,
                                           2048, 2048, 2048, 2048);
    // K projection -> fp16 hi/lo
    mma_gemm_f16<1><<<dim3(16, 8), 256>>>(at16h, Wk16h, Wk16l, bk,
                                          nullptr, nullptr, K16h, K16l,
                                          2048, 2048, 2048, 2048);
    // V projection (A=Wv16, B=at hi/lo) -> Vt fp16 hi/lo [b,h,d,t]
    mma_gemm_f16<2><<<dim3(8, 16), 256>>>(Wv16, at16h, at16l, bv,
                                          nullptr, nullptr, Vt16h, Vt16l,
                                          2048, 2048, 2048, 0);
    // Fused scores + softmax + PV -> ctx fp16 (64 q-rows/CTA, occ 2)
    fused_attn_kernel<<<dim3(1, 32, 64), 256, AS_SMEM>>>(Q16, K16h, K16l,
                                                         Vt16h, Vt16l, mask, C16);
    // O projection -> fp32
    mma_gemm_f16<4><<<dim3(16, 64), 256>>>(C16, Wo16h, Wo16l, bo,
                                           Db, nullptr, nullptr, nullptr,
                                           2048, 2048, 2048, 2048);
    // residual scale + LayerNorm
    ln_kernel<<<8192, 256>>>(Db, gamma, beta, rsp, out);
}